// round 1
// baseline (speedup 1.0000x reference)
#include <cuda_runtime.h>

#define B 64
#define C 128
#define H 32
#define W 32
#define HW 1024
#define OUTC 640
#define WS_STRIDE 132  // padded oc-stride for 1x1 weight smem (bank-conflict relief, 16B aligned)

// ---------------- device scratch (allocation-free rule: __device__ globals) ---------------
__device__ float g_s0[B * C * HW];                 // 32 MB  preprocess0 output
__device__ float g_s1[B * C * HW];                 // 32 MB  preprocess1 output
__device__ float g_alpha[8][5];                    // softmaxed alphas
__device__ float g_wcomb[8 * C * 18 * C];          // [edge][ic][tap(0..8 conv,9..17 dil)][oc], pre-scaled

// ---------------- softmax over alpha rows ----------------
__global__ void softmax_kernel(const float* __restrict__ alphas) {
    int r = threadIdx.x;
    if (r < 8) {
        float m = -3.4e38f;
        #pragma unroll
        for (int j = 0; j < 5; j++) m = fmaxf(m, alphas[r * 5 + j]);
        float e[5], s = 0.f;
        #pragma unroll
        for (int j = 0; j < 5; j++) { e[j] = expf(alphas[r * 5 + j] - m); s += e[j]; }
        float inv = 1.f / s;
        #pragma unroll
        for (int j = 0; j < 5; j++) g_alpha[r][j] = e[j] * inv;
    }
}

// ---------------- weight transpose + alpha pre-scale ----------------
// g_wcomb[((e*C+ic)*18 + tap)*C + oc] = tap<9 ? a[e][1]*wc[e][oc][ic][tap]
//                                             : a[e][2]*wd[e][oc][ic][tap-9]
__global__ void prep_w_kernel(const float* __restrict__ wc, const float* __restrict__ wd) {
    int idx = blockIdx.x * blockDim.x + threadIdx.x;
    if (idx >= 8 * C * 18 * C) return;
    int oc = idx & 127;
    int rest = idx >> 7;
    int tap = rest % 18;
    int rest2 = rest / 18;
    int ic = rest2 & 127;
    int e = rest2 >> 7;
    float v;
    if (tap < 9) v = g_alpha[e][1] * wc[((e * C + oc) * C + ic) * 9 + tap];
    else         v = g_alpha[e][2] * wd[((e * C + oc) * C + ic) * 9 + (tap - 9)];
    g_wcomb[idx] = v;
}

// ---------------- 1x1 conv (preprocess): out[n][oc][p] = sum_ic w[oc][ic]*in[n][ic][p] ----------------
// grid 1024 (=64 batches x 16 pixel-chunks of 64), 256 threads, dynamic smem
__global__ __launch_bounds__(256) void conv1x1_kernel(const float* __restrict__ in,
                                                      const float* __restrict__ w,
                                                      float* __restrict__ out) {
    extern __shared__ float sm[];
    float* ws = sm;                    // [ic][oc] stride WS_STRIDE  (transposed)
    float* ins = sm + C * WS_STRIDE;   // [ic][64 px]
    int t = threadIdx.x;
    int n = blockIdx.x >> 4;
    int hw0 = (blockIdx.x & 15) << 6;

    for (int i = t; i < C * C; i += 256) {
        int oc = i >> 7, ic = i & 127;           // coalesced global read
        ws[ic * WS_STRIDE + oc] = w[i];          // (oc=i>>7 constant per warp chunk)
    }
    const float4* inb = (const float4*)(in + (long)n * C * HW + hw0);
    float4* insv = (float4*)ins;
    for (int i = t; i < C * 16; i += 256) {      // 16 float4 per ic row
        int ic = i >> 4, p4 = i & 15;
        insv[ic * 16 + p4] = inb[ic * (HW / 4) + p4];
    }
    __syncthreads();

    int pg = t & 15, og = t >> 4;
    int ocb = og * 8;
    float acc[4][8];
    #pragma unroll
    for (int k = 0; k < 4; k++)
        #pragma unroll
        for (int j = 0; j < 8; j++) acc[k][j] = 0.f;

    for (int ic = 0; ic < C; ic++) {
        float4 iv = *(const float4*)&ins[ic * 64 + pg * 4];
        float4 wa = *(const float4*)&ws[ic * WS_STRIDE + ocb];
        float4 wb = *(const float4*)&ws[ic * WS_STRIDE + ocb + 4];
        float xv[4] = {iv.x, iv.y, iv.z, iv.w};
        float wv[8] = {wa.x, wa.y, wa.z, wa.w, wb.x, wb.y, wb.z, wb.w};
        #pragma unroll
        for (int k = 0; k < 4; k++)
            #pragma unroll
            for (int j = 0; j < 8; j++) acc[k][j] += xv[k] * wv[j];
    }

    float* ob = out + (long)n * C * HW + hw0 + pg * 4;
    #pragma unroll
    for (int j = 0; j < 8; j++) {
        float4 o = make_float4(acc[0][j], acc[1][j], acc[2][j], acc[3][j]);
        *(float4*)&ob[(ocb + j) * HW] = o;
    }
}

// ---------------- fused node kernel ----------------
// s_out = a0(e0)*h0 + conv(h0, a1*Wc_e0) + dil(h0, a2*Wd_e0) + a3(e0)*avg(h0) + a4(e0)*max(h0)
//        + same for (h1, e1)
// grid (16 tiles, 64 batch), 256 threads. Tile 8x8 px, all 128 oc.
__global__ __launch_bounds__(256) void node_kernel(const float* __restrict__ h0, int h0_bs,
                                                   const float* __restrict__ h1, int h1_bs,
                                                   int e0, int e1,
                                                   float* __restrict__ out) {
    __shared__ float in_t[12 * 12];
    __shared__ float ws[18 * 128];

    int t = threadIdx.x;
    int pg = t & 15, og = t >> 4;
    int r = pg >> 1, cb = (pg & 1) * 4;
    int ocb = og * 8;
    int b = blockIdx.y;
    int tile = blockIdx.x;
    int y0 = (tile >> 2) * 8, x0 = (tile & 3) * 8;

    float acc[4][8];
    #pragma unroll
    for (int k = 0; k < 4; k++)
        #pragma unroll
        for (int j = 0; j < 8; j++) acc[k][j] = 0.f;

    float a0A = g_alpha[e0][0], a3A = g_alpha[e0][3] * (1.f / 9.f), a4A = g_alpha[e0][4];
    float a0B = g_alpha[e1][0], a3B = g_alpha[e1][3] * (1.f / 9.f), a4B = g_alpha[e1][4];

    const float* hb0 = h0 + (long)b * h0_bs;
    const float* hb1 = h1 + (long)b * h1_bs;

    for (int ic = 0; ic < 2 * C; ic++) {
        int ch = ic & 127;
        const float* hb = (ic < C) ? hb0 : hb1;
        int e = (ic < C) ? e0 : e1;

        __syncthreads();
        if (t < 144) {
            int rr = t / 12, cc = t - rr * 12;
            int gy = y0 + rr - 2, gx = x0 + cc - 2;
            float v = 0.f;
            if ((unsigned)gy < 32u && (unsigned)gx < 32u) v = hb[ch * HW + (gy << 5) + gx];
            in_t[rr * 12 + cc] = v;
        }
        const float* wsrc = g_wcomb + (long)(e * C + ch) * 18 * C;
        #pragma unroll
        for (int j = 0; j < 9; j++) ws[t + j * 256] = wsrc[t + j * 256];
        __syncthreads();

        // stage 5 rows x 8 cols from the tile into registers (16B-aligned: 12*row + cb)
        float iv[5][8];
        #pragma unroll
        for (int dy = 0; dy < 5; dy++) {
            float4 va = *(const float4*)&in_t[(r + dy) * 12 + cb];
            float4 vb = *(const float4*)&in_t[(r + dy) * 12 + cb + 4];
            iv[dy][0] = va.x; iv[dy][1] = va.y; iv[dy][2] = va.z; iv[dy][3] = va.w;
            iv[dy][4] = vb.x; iv[dy][5] = vb.y; iv[dy][6] = vb.z; iv[dy][7] = vb.w;
        }

        #pragma unroll
        for (int ty = 0; ty < 3; ty++) {
            #pragma unroll
            for (int tx = 0; tx < 3; tx++) {
                int tap = ty * 3 + tx;
                float4 wa = *(const float4*)&ws[tap * 128 + ocb];
                float4 wb = *(const float4*)&ws[tap * 128 + ocb + 4];
                #pragma unroll
                for (int k = 0; k < 4; k++) {
                    float x = iv[ty + 1][tx + 1 + k];
                    acc[k][0] += x * wa.x; acc[k][1] += x * wa.y;
                    acc[k][2] += x * wa.z; acc[k][3] += x * wa.w;
                    acc[k][4] += x * wb.x; acc[k][5] += x * wb.y;
                    acc[k][6] += x * wb.z; acc[k][7] += x * wb.w;
                }
                float4 da = *(const float4*)&ws[(9 + tap) * 128 + ocb];
                float4 db = *(const float4*)&ws[(9 + tap) * 128 + ocb + 4];
                #pragma unroll
                for (int k = 0; k < 4; k++) {
                    float x = iv[ty * 2][tx * 2 + k];
                    acc[k][0] += x * da.x; acc[k][1] += x * da.y;
                    acc[k][2] += x * da.z; acc[k][3] += x * da.w;
                    acc[k][4] += x * db.x; acc[k][5] += x * db.y;
                    acc[k][6] += x * db.z; acc[k][7] += x * db.w;
                }
            }
        }

        // identity + avg pool + max pool, only the thread group owning oc == ch
        if ((ch >> 3) == og) {
            float a0, a3, a4;
            if (ic < C) { a0 = a0A; a3 = a3A; a4 = a4A; }
            else        { a0 = a0B; a3 = a3B; a4 = a4B; }
            int l = ch & 7;
            #pragma unroll
            for (int k = 0; k < 4; k++) {
                float s9 = 0.f, m = -3.4e38f;
                #pragma unroll
                for (int dy = -1; dy <= 1; dy++) {
                    #pragma unroll
                    for (int dx = -1; dx <= 1; dx++) {
                        float val = iv[2 + dy][2 + dx + k];
                        s9 += val;   // zero-padded tile -> count_include_pad avg is correct
                        int gy = y0 + r + dy, gx = x0 + cb + k + dx;
                        if ((unsigned)gy < 32u && (unsigned)gx < 32u) m = fmaxf(m, val);
                    }
                }
                float p = a0 * iv[2][2 + k] + a3 * s9 + a4 * m;
                #pragma unroll
                for (int j = 0; j < 8; j++) if (j == l) acc[k][j] += p;
            }
        }
    }

    float* ob = out + (long)b * (OUTC * HW) + (y0 + r) * W + x0 + cb;
    #pragma unroll
    for (int j = 0; j < 8; j++) {
        float4 o = make_float4(acc[0][j], acc[1][j], acc[2][j], acc[3][j]);
        *(float4*)&ob[(ocb + j) * HW] = o;
    }
}

// ---------------- skip copies: out[:,512:640,:,:] = skip ; tuple tail = skip ----------------
__global__ void copy_skip_kernel(const float* __restrict__ skip, float* __restrict__ out) {
    int idx = blockIdx.x * blockDim.x + threadIdx.x;   // over B*C*HW/4 = 2097152 float4
    float4 v = ((const float4*)skip)[idx];
    int hw4 = idx & 255;
    int c = (idx >> 8) & 127;
    int n = idx >> 15;
    ((float4*)out)[(long)n * (OUTC * HW / 4) + (512 + c) * (HW / 4) + hw4] = v;
    ((float4*)out)[(long)B * OUTC * HW / 4 + idx] = v;
}

// ---------------- launch ----------------
extern "C" void kernel_launch(void* const* d_in, const int* in_sizes, int n_in,
                              void* d_out, int out_size) {
    const float* input0  = (const float*)d_in[0];
    const float* input1  = (const float*)d_in[1];
    const float* skip    = (const float*)d_in[2];
    const float* w_pre0  = (const float*)d_in[3];
    const float* w_pre1  = (const float*)d_in[4];
    const float* w_conv3 = (const float*)d_in[5];
    const float* w_dil3  = (const float*)d_in[6];
    const float* alphas  = (const float*)d_in[7];
    float* out = (float*)d_out;

    float *s0, *s1;
    cudaGetSymbolAddress((void**)&s0, g_s0);
    cudaGetSymbolAddress((void**)&s1, g_s1);

    softmax_kernel<<<1, 32>>>(alphas);
    prep_w_kernel<<<(8 * C * 18 * C) / 256, 256>>>(w_conv3, w_dil3);

    const int smem1x1 = (C * WS_STRIDE + C * 64) * sizeof(float);  // ~100 KB
    cudaFuncSetAttribute(conv1x1_kernel, cudaFuncAttributeMaxDynamicSharedMemorySize, smem1x1);
    conv1x1_kernel<<<1024, 256, smem1x1>>>(input0, w_pre0, s0);
    conv1x1_kernel<<<1024, 256, smem1x1>>>(input1, w_pre1, s1);

    dim3 ngrid(16, 64);
    // node 0: h0=s0, h1=s1 -> slice 0
    node_kernel<<<ngrid, 256>>>(s0, C * HW, s1, C * HW, 0, 1, out + 0 * C * HW);
    // node 1: h0=s1, h1=s2(slice0) -> slice 1
    node_kernel<<<ngrid, 256>>>(s1, C * HW, out + 0 * C * HW, OUTC * HW, 2, 3, out + 1 * C * HW);
    // node 2: h0=s2, h1=s3 -> slice 2
    node_kernel<<<ngrid, 256>>>(out + 0 * C * HW, OUTC * HW, out + 1 * C * HW, OUTC * HW, 4, 5,
                                out + 2 * C * HW);
    // node 3: h0=s3, h1=s4 -> slice 3
    node_kernel<<<ngrid, 256>>>(out + 1 * C * HW, OUTC * HW, out + 2 * C * HW, OUTC * HW, 6, 7,
                                out + 3 * C * HW);

    copy_skip_kernel<<<(B * C * HW / 4) / 256, 256>>>(skip, out);
}